// round 6
// baseline (speedup 1.0000x reference)
#include <cuda_runtime.h>
#include <cstdint>
#include <cstddef>

#define B_  256
#define L_  2048
#define H_  128
#define H2_ 256
#define V_  32000

// ---------------- scratch (static device globals; no allocs allowed) ----------------
__device__ float g_h[(size_t)B_ * L_ * H_];   // encoded h_all [B,L,H]
__device__ float g_r[B_ * H_];
__device__ float g_r2[B_ * H_];

// ============================ mma helpers (baseline PTX) ============================
__device__ __forceinline__ uint32_t f2tf32(float x) {
    uint32_t r;
    asm("cvt.rna.tf32.f32 %0, %1;" : "=r"(r) : "f"(x));
    return r;
}
__device__ __forceinline__ void mma_tf32(float* c, const uint32_t* a, const uint32_t* b) {
    asm volatile("mma.sync.aligned.m16n8k8.row.col.f32.tf32.tf32.f32 "
        "{%0,%1,%2,%3}, {%4,%5,%6,%7}, {%8,%9}, {%0,%1,%2,%3};"
        : "+f"(c[0]), "+f"(c[1]), "+f"(c[2]), "+f"(c[3])
        : "r"(a[0]), "r"(a[1]), "r"(a[2]), "r"(a[3]), "r"(b[0]), "r"(b[1]));
}
__device__ __forceinline__ void tsplit(float x, uint32_t& h, uint32_t& m) {
    h = f2tf32(x);
    m = f2tf32(x - __uint_as_float(h));
}

// =====================================================================
// Encode: 64 tokens/CTA, 256 threads (8 warps, 4x2 warp grid).
// Weights pre-split to (h,m) tf32 in SMEM at chunk-load time (fast path),
// FULL 4-pass split MMA (hh, hm, mh, mm) in R3's exact accumulation order
// -> h output is bit-identical to the R3 kernel that passed.
// =====================================================================
#define EPAD 132
#define UPAD 260
#define WPAD1 132
#define WPAD2 68
#define OFF_E  0
#define OFF_U  (64 * EPAD)                       // 8448
#define OFF_WH (64 * EPAD + 64 * UPAD)           // 25088
#define OFF_WM (OFF_WH + 8704)                   // 33792
#define ENC_FLOATS (OFF_WM + 8704)               // 42496
#define ENC_SMEM (ENC_FLOATS * 4)                // 169984 B

__global__ void __launch_bounds__(256, 1) encode_mma(
    const int*   __restrict__ seq,   const float* __restrict__ embed,
    const float* __restrict__ W1,    const float* __restrict__ b1,
    const float* __restrict__ W2,    const float* __restrict__ b2,
    const float* __restrict__ gamma, const float* __restrict__ beta)
{
    extern __shared__ float sm[];
    float*    eBuf = sm + OFF_E;                 // [64][132] f32
    float*    uBuf = sm + OFF_U;                 // [64][260] f32
    uint32_t* wh   = (uint32_t*)(sm + OFF_WH);   // weight hi split
    uint32_t* wm   = (uint32_t*)(sm + OFF_WM);   // weight mid split

    const int tid  = threadIdx.x;
    const int w    = tid >> 5, lane = tid & 31;
    const int wy   = w >> 1,   wx   = w & 1;
    const int gr   = lane >> 2, gc  = lane & 3;
    const int tok0 = blockIdx.x * 64;

    for (int i = tid; i < 64 * 128; i += 256) {
        int row = i >> 7, col = i & 127;
        int s = seq[tok0 + row];
        eBuf[row * EPAD + col] = embed[(size_t)s * 128 + col];
    }

    const int ar0 = (wy * 16 + gr) * EPAD;
    const int ar1 = (wy * 16 + gr + 8) * EPAD;

    // ---------------- GEMM1: 4 N-chunks of 64 ----------------
    for (int c = 0; c < 4; c++) {
        __syncthreads();
        for (int i = tid; i < 64 * 128; i += 256) {    // split W1 chunk -> wh/wm
            int n = i & 63, k = i >> 6;
            float v = W1[k * H2_ + 64 * c + n];
            uint32_t h, m;
            tsplit(v, h, m);
            wh[n * WPAD1 + k] = h;
            wm[n * WPAD1 + k] = m;
        }
        __syncthreads();

        float acc[4][4];
        #pragma unroll
        for (int nf = 0; nf < 4; nf++)
            #pragma unroll
            for (int j = 0; j < 4; j++) acc[nf][j] = 0.f;

        #pragma unroll 4
        for (int ks = 0; ks < 16; ks++) {
            int k0 = ks * 8;
            uint32_t ah[4], am[4];
            tsplit(eBuf[ar0 + k0 + gc],     ah[0], am[0]);
            tsplit(eBuf[ar1 + k0 + gc],     ah[1], am[1]);
            tsplit(eBuf[ar0 + k0 + 4 + gc], ah[2], am[2]);
            tsplit(eBuf[ar1 + k0 + 4 + gc], ah[3], am[3]);
            #pragma unroll
            for (int nf = 0; nf < 4; nf++) {
                int n = wx * 32 + nf * 8 + gr;
                uint32_t bh[2], bm[2];
                bh[0] = wh[n * WPAD1 + k0 + gc];
                bm[0] = wm[n * WPAD1 + k0 + gc];
                bh[1] = wh[n * WPAD1 + k0 + 4 + gc];
                bm[1] = wm[n * WPAD1 + k0 + 4 + gc];
                mma_tf32(acc[nf], ah, bh);
                mma_tf32(acc[nf], ah, bm);
                mma_tf32(acc[nf], am, bh);
                mma_tf32(acc[nf], am, bm);     // restored: R3 bit-exact order
            }
        }
        #pragma unroll
        for (int nf = 0; nf < 4; nf++)
            #pragma unroll
            for (int j = 0; j < 4; j++) {
                int row = wy * 16 + gr + ((j >> 1) ? 8 : 0);
                int col = 64 * c + wx * 32 + nf * 8 + gc * 2 + (j & 1);
                uBuf[row * UPAD + col] = fmaxf(acc[nf][j] + __ldg(b1 + col), 0.f);
            }
    }

    // ---------------- GEMM2: 4 K-chunks of 64 ----------------
    float acc2[8][4];
    #pragma unroll
    for (int nf = 0; nf < 8; nf++)
        #pragma unroll
        for (int j = 0; j < 4; j++) acc2[nf][j] = 0.f;

    const int ur0 = (wy * 16 + gr) * UPAD;
    const int ur1 = (wy * 16 + gr + 8) * UPAD;

    for (int c2 = 0; c2 < 4; c2++) {
        __syncthreads();
        for (int i = tid; i < 128 * 64; i += 256) {    // split W2 chunk -> wh/wm
            int n = i & 127, kk = i >> 7;
            float v = W2[(64 * c2 + kk) * H_ + n];
            uint32_t h, m;
            tsplit(v, h, m);
            wh[n * WPAD2 + kk] = h;
            wm[n * WPAD2 + kk] = m;
        }
        __syncthreads();

        #pragma unroll 4
        for (int ks = 0; ks < 8; ks++) {
            int kg = 64 * c2 + ks * 8;
            int kl = ks * 8;
            uint32_t ah[4], am[4];
            tsplit(uBuf[ur0 + kg + gc],     ah[0], am[0]);
            tsplit(uBuf[ur1 + kg + gc],     ah[1], am[1]);
            tsplit(uBuf[ur0 + kg + 4 + gc], ah[2], am[2]);
            tsplit(uBuf[ur1 + kg + 4 + gc], ah[3], am[3]);
            #pragma unroll
            for (int nf = 0; nf < 8; nf++) {
                int n = wx * 64 + nf * 8 + gr;
                uint32_t bh[2], bm[2];
                bh[0] = wh[n * WPAD2 + kl + gc];
                bm[0] = wm[n * WPAD2 + kl + gc];
                bh[1] = wh[n * WPAD2 + kl + 4 + gc];
                bm[1] = wm[n * WPAD2 + kl + 4 + gc];
                mma_tf32(acc2[nf], ah, bh);
                mma_tf32(acc2[nf], ah, bm);
                mma_tf32(acc2[nf], am, bh);
                mma_tf32(acc2[nf], am, bm);    // restored: R3 bit-exact order
            }
        }
    }

    // ---------------- epilogue: y = acc2 + b2 + e ; LayerNorm ----------------
    __syncthreads();
    float* yBuf = (float*)wh;        // 8704 floats >= 64*132
    #pragma unroll
    for (int nf = 0; nf < 8; nf++)
        #pragma unroll
        for (int j = 0; j < 4; j++) {
            int row = wy * 16 + gr + ((j >> 1) ? 8 : 0);
            int col = wx * 64 + nf * 8 + gc * 2 + (j & 1);
            yBuf[row * EPAD + col] = acc2[nf][j] + __ldg(b2 + col) + eBuf[row * EPAD + col];
        }
    __syncthreads();

    #pragma unroll
    for (int rr = 0; rr < 8; rr++) {
        int row = w * 8 + rr;
        float v[4];
        #pragma unroll
        for (int q = 0; q < 4; q++) v[q] = yBuf[row * EPAD + lane + 32 * q];
        float s = v[0] + v[1] + v[2] + v[3];
        #pragma unroll
        for (int o = 16; o; o >>= 1) s += __shfl_xor_sync(0xffffffffu, s, o);
        float mu = s * (1.f / 128.f);
        float d[4], sq = 0.f;
        #pragma unroll
        for (int q = 0; q < 4; q++) { d[q] = v[q] - mu; sq = fmaf(d[q], d[q], sq); }
        #pragma unroll
        for (int o = 16; o; o >>= 1) sq += __shfl_xor_sync(0xffffffffu, sq, o);
        float inv = rsqrtf(sq * (1.f / 128.f) + 1e-5f);
        size_t base = (size_t)(tok0 + row) * H_;
        #pragma unroll
        for (int q = 0; q < 4; q++) {
            int col = lane + 32 * q;
            g_h[base + col] = d[q] * inv * __ldg(gamma + col) + __ldg(beta + col);
        }
    }
}

// =====================================================================
// Kernel 2: energy-gated delta scan — R1/R3 verbatim (known-pass arithmetic)
// =====================================================================
__global__ void __launch_bounds__(256, 2) scan_kernel()
{
    __shared__ float k_s[128];
    __shared__ float err_s[128];
    __shared__ float vp_part[128][17];
    __shared__ float red[8];

    const int b   = blockIdx.x;
    const int tid = threadIdx.x;
    const int ty  = tid >> 4, tx = tid & 15;
    const float* __restrict__ hb = g_h + (size_t)b * L_ * H_;

    float M[8][8];
    #pragma unroll
    for (int r = 0; r < 8; r++)
        #pragma unroll
        for (int c = 0; c < 8; c++) M[r][c] = 0.f;

    float knext = 0.f;
    if (tid < 128) knext = hb[tid];

    for (int t = 0; t < L_; t++) {
        __syncthreads();
        if (tid < 128) {
            float kv = knext;
            k_s[tid] = kv;
            float p = kv * kv;
            #pragma unroll
            for (int o = 16; o; o >>= 1) p += __shfl_xor_sync(0xffffffffu, p, o);
            if ((tid & 31) == 0) red[tid >> 5] = p;
            if (t + 1 < L_) knext = hb[(size_t)(t + 1) * H_ + tid];
        }
        __syncthreads();

        float kreg[8];
        #pragma unroll
        for (int c = 0; c < 8; c++) kreg[c] = k_s[tx * 8 + c];
        #pragma unroll
        for (int r = 0; r < 8; r++) {
            float s = 0.f;
            #pragma unroll
            for (int c = 0; c < 8; c++) s = fmaf(M[r][c], kreg[c], s);
            vp_part[ty * 8 + r][tx] = s;
        }
        __syncthreads();

        if (tid < 128) {
            float vp = 0.f;
            #pragma unroll
            for (int x = 0; x < 16; x++) vp += vp_part[tid][x];
            float kk = red[0] + red[1] + red[2] + red[3];
            if (t == L_ - 1) {
                g_r[b * H_ + tid] = vp;
            } else {
                float e = k_s[tid] - vp / (kk + 1e-6f);
                err_s[tid] = e;
                float p = e * e;
                #pragma unroll
                for (int o = 16; o; o >>= 1) p += __shfl_xor_sync(0xffffffffu, p, o);
                if ((tid & 31) == 0) red[4 + (tid >> 5)] = p;
            }
        }
        __syncthreads();

        if (t < L_ - 1) {
            float e2 = red[4] + red[5] + red[6] + red[7];
            float kk = red[0] + red[1] + red[2] + red[3];
            if (sqrtf(e2) > 0.4f * sqrtf(kk)) {
                float er[8];
                #pragma unroll
                for (int r = 0; r < 8; r++) er[r] = err_s[ty * 8 + r];
                #pragma unroll
                for (int r = 0; r < 8; r++)
                    #pragma unroll
                    for (int c = 0; c < 8; c++) M[r][c] = fmaf(er[r], kreg[c], M[r][c]);
            }
        }
    }
}

// =====================================================================
// Kernel 3: r2 = r @ Wrp + brp
// =====================================================================
__global__ void __launch_bounds__(256, 1) rproj_kernel(
    const float* __restrict__ Wrp, const float* __restrict__ brp)
{
    extern __shared__ float smf[];
    float* Rs = smf;
    float* Ws = smf + 64 * 132;
    const int tid = threadIdx.x, ty = tid >> 4, tx = tid & 15;
    const int m0 = blockIdx.x * 64;

    for (int i = tid; i < 64 * 128; i += 256) {
        int r = i >> 7, c = i & 127;
        Rs[r * 132 + c] = g_r[(m0 + r) * H_ + c];
    }
    for (int i = tid; i < 128 * 128; i += 256) Ws[i] = Wrp[i];
    __syncthreads();

    float acc[4][8];
    #pragma unroll
    for (int r = 0; r < 4; r++)
        #pragma unroll
        for (int j = 0; j < 8; j++) acc[r][j] = 0.f;
    #pragma unroll 8
    for (int k = 0; k < 128; k++) {
        float a[4], bb[8];
        #pragma unroll
        for (int r = 0; r < 4; r++) a[r] = Rs[(ty * 4 + r) * 132 + k];
        #pragma unroll
        for (int j = 0; j < 8; j++) bb[j] = Ws[k * 128 + tx + 16 * j];
        #pragma unroll
        for (int r = 0; r < 4; r++)
            #pragma unroll
            for (int j = 0; j < 8; j++) acc[r][j] = fmaf(a[r], bb[j], acc[r][j]);
    }
    #pragma unroll
    for (int r = 0; r < 4; r++)
        #pragma unroll
        for (int j = 0; j < 8; j++) {
            int rr = m0 + ty * 4 + r, cc = tx + 16 * j;
            g_r2[rr * H_ + cc] = acc[r][j] + brp[cc];
        }
}

// =====================================================================
// Kernel 4: out = r2 @ Wout + bout
// =====================================================================
__global__ void __launch_bounds__(256, 1) out_kernel(
    const float* __restrict__ Wout, const float* __restrict__ bout,
    float* __restrict__ out)
{
    extern __shared__ float smf[];
    float* Rs = smf;
    float* Ws = smf + 64 * 132;
    const int tid = threadIdx.x, ty = tid >> 4, tx = tid & 15;
    const int n0 = blockIdx.x * 128;
    const int m0 = blockIdx.y * 64;

    for (int i = tid; i < 64 * 128; i += 256) {
        int r = i >> 7, c = i & 127;
        Rs[r * 132 + c] = g_r2[(m0 + r) * H_ + c];
    }
    for (int i = tid; i < 128 * 128; i += 256) {
        int k = i >> 7, c = i & 127;
        Ws[i] = Wout[(size_t)k * V_ + n0 + c];
    }
    __syncthreads();

    float acc[4][8];
    #pragma unroll
    for (int r = 0; r < 4; r++)
        #pragma unroll
        for (int j = 0; j < 8; j++) acc[r][j] = 0.f;
    #pragma unroll 8
    for (int k = 0; k < 128; k++) {
        float a[4], bb[8];
        #pragma unroll
        for (int r = 0; r < 4; r++) a[r] = Rs[(ty * 4 + r) * 132 + k];
        #pragma unroll
        for (int j = 0; j < 8; j++) bb[j] = Ws[k * 128 + tx + 16 * j];
        #pragma unroll
        for (int r = 0; r < 4; r++)
            #pragma unroll
            for (int j = 0; j < 8; j++) acc[r][j] = fmaf(a[r], bb[j], acc[r][j]);
    }
    #pragma unroll
    for (int r = 0; r < 4; r++)
        #pragma unroll
        for (int j = 0; j < 8; j++) {
            int rr = m0 + ty * 4 + r, cc = n0 + tx + 16 * j;
            out[(size_t)rr * V_ + cc] = acc[r][j] + bout[cc];
        }
}

// =====================================================================
// launcher
// =====================================================================
extern "C" void kernel_launch(void* const* d_in, const int* in_sizes, int n_in,
                              void* d_out, int out_size)
{
    const int*   seq   = (const int*)  d_in[0];
    const float* embed = (const float*)d_in[1];
    const float* W1    = (const float*)d_in[2];
    const float* b1    = (const float*)d_in[3];
    const float* W2    = (const float*)d_in[4];
    const float* b2    = (const float*)d_in[5];
    const float* gamma = (const float*)d_in[6];
    const float* beta  = (const float*)d_in[7];
    const float* Wrp   = (const float*)d_in[8];
    const float* brp   = (const float*)d_in[9];
    const float* Wout  = (const float*)d_in[10];
    const float* bout  = (const float*)d_in[11];
    float* out = (float*)d_out;

    const int PROJ_SMEM = (64 * 132 + 128 * 128) * 4;

    cudaFuncSetAttribute(encode_mma,   cudaFuncAttributeMaxDynamicSharedMemorySize, ENC_SMEM);
    cudaFuncSetAttribute(rproj_kernel, cudaFuncAttributeMaxDynamicSharedMemorySize, PROJ_SMEM);
    cudaFuncSetAttribute(out_kernel,   cudaFuncAttributeMaxDynamicSharedMemorySize, PROJ_SMEM);

    encode_mma<<<(B_ * L_) / 64, 256, ENC_SMEM>>>(seq, embed, W1, b1, W2, b2, gamma, beta);
    scan_kernel<<<B_, 256>>>();
    rproj_kernel<<<B_ / 64, 256, PROJ_SMEM>>>(Wrp, brp);
    out_kernel<<<dim3(V_ / 128, B_ / 64), 256, PROJ_SMEM>>>(Wout, bout, out);
}

// round 7
// speedup vs baseline: 1.0175x; 1.0175x over previous
#include <cuda_runtime.h>
#include <cstdint>
#include <cstddef>

#define B_  256
#define L_  2048
#define H_  128
#define H2_ 256
#define V_  32000

// ---------------- scratch (static device globals; no allocs allowed) ----------------
__device__ float g_h[(size_t)B_ * L_ * H_];   // encoded h_all [B,L,H]
__device__ float g_r[B_ * H_];
__device__ float g_r2[B_ * H_];

// ============================ mma helpers (baseline PTX) ============================
__device__ __forceinline__ uint32_t f2tf32(float x) {
    uint32_t r;
    asm("cvt.rna.tf32.f32 %0, %1;" : "=r"(r) : "f"(x));
    return r;
}
__device__ __forceinline__ void mma_tf32(float* c, const uint32_t* a, const uint32_t* b) {
    asm volatile("mma.sync.aligned.m16n8k8.row.col.f32.tf32.tf32.f32 "
        "{%0,%1,%2,%3}, {%4,%5,%6,%7}, {%8,%9}, {%0,%1,%2,%3};"
        : "+f"(c[0]), "+f"(c[1]), "+f"(c[2]), "+f"(c[3])
        : "r"(a[0]), "r"(a[1]), "r"(a[2]), "r"(a[3]), "r"(b[0]), "r"(b[1]));
}
__device__ __forceinline__ void tsplit(float x, uint32_t& h, uint32_t& m) {
    h = f2tf32(x);
    m = f2tf32(x - __uint_as_float(h));
}

// =====================================================================
// Encode (unchanged from R5 — bit-identical output, passed)
// =====================================================================
#define EPAD 132
#define UPAD 260
#define WPAD1 132
#define WPAD2 68
#define OFF_E  0
#define OFF_U  (64 * EPAD)
#define OFF_WH (64 * EPAD + 64 * UPAD)
#define OFF_WM (OFF_WH + 8704)
#define ENC_FLOATS (OFF_WM + 8704)
#define ENC_SMEM (ENC_FLOATS * 4)

__global__ void __launch_bounds__(256, 1) encode_mma(
    const int*   __restrict__ seq,   const float* __restrict__ embed,
    const float* __restrict__ W1,    const float* __restrict__ b1,
    const float* __restrict__ W2,    const float* __restrict__ b2,
    const float* __restrict__ gamma, const float* __restrict__ beta)
{
    extern __shared__ float sm[];
    float*    eBuf = sm + OFF_E;
    float*    uBuf = sm + OFF_U;
    uint32_t* wh   = (uint32_t*)(sm + OFF_WH);
    uint32_t* wm   = (uint32_t*)(sm + OFF_WM);

    const int tid  = threadIdx.x;
    const int w    = tid >> 5, lane = tid & 31;
    const int wy   = w >> 1,   wx   = w & 1;
    const int gr   = lane >> 2, gc  = lane & 3;
    const int tok0 = blockIdx.x * 64;

    for (int i = tid; i < 64 * 128; i += 256) {
        int row = i >> 7, col = i & 127;
        int s = seq[tok0 + row];
        eBuf[row * EPAD + col] = embed[(size_t)s * 128 + col];
    }

    const int ar0 = (wy * 16 + gr) * EPAD;
    const int ar1 = (wy * 16 + gr + 8) * EPAD;

    for (int c = 0; c < 4; c++) {
        __syncthreads();
        for (int i = tid; i < 64 * 128; i += 256) {
            int n = i & 63, k = i >> 6;
            float v = W1[k * H2_ + 64 * c + n];
            uint32_t h, m;
            tsplit(v, h, m);
            wh[n * WPAD1 + k] = h;
            wm[n * WPAD1 + k] = m;
        }
        __syncthreads();

        float acc[4][4];
        #pragma unroll
        for (int nf = 0; nf < 4; nf++)
            #pragma unroll
            for (int j = 0; j < 4; j++) acc[nf][j] = 0.f;

        #pragma unroll 4
        for (int ks = 0; ks < 16; ks++) {
            int k0 = ks * 8;
            uint32_t ah[4], am[4];
            tsplit(eBuf[ar0 + k0 + gc],     ah[0], am[0]);
            tsplit(eBuf[ar1 + k0 + gc],     ah[1], am[1]);
            tsplit(eBuf[ar0 + k0 + 4 + gc], ah[2], am[2]);
            tsplit(eBuf[ar1 + k0 + 4 + gc], ah[3], am[3]);
            #pragma unroll
            for (int nf = 0; nf < 4; nf++) {
                int n = wx * 32 + nf * 8 + gr;
                uint32_t bh[2], bm[2];
                bh[0] = wh[n * WPAD1 + k0 + gc];
                bm[0] = wm[n * WPAD1 + k0 + gc];
                bh[1] = wh[n * WPAD1 + k0 + 4 + gc];
                bm[1] = wm[n * WPAD1 + k0 + 4 + gc];
                mma_tf32(acc[nf], ah, bh);
                mma_tf32(acc[nf], ah, bm);
                mma_tf32(acc[nf], am, bh);
                mma_tf32(acc[nf], am, bm);
            }
        }
        #pragma unroll
        for (int nf = 0; nf < 4; nf++)
            #pragma unroll
            for (int j = 0; j < 4; j++) {
                int row = wy * 16 + gr + ((j >> 1) ? 8 : 0);
                int col = 64 * c + wx * 32 + nf * 8 + gc * 2 + (j & 1);
                uBuf[row * UPAD + col] = fmaxf(acc[nf][j] + __ldg(b1 + col), 0.f);
            }
    }

    float acc2[8][4];
    #pragma unroll
    for (int nf = 0; nf < 8; nf++)
        #pragma unroll
        for (int j = 0; j < 4; j++) acc2[nf][j] = 0.f;

    const int ur0 = (wy * 16 + gr) * UPAD;
    const int ur1 = (wy * 16 + gr + 8) * UPAD;

    for (int c2 = 0; c2 < 4; c2++) {
        __syncthreads();
        for (int i = tid; i < 128 * 64; i += 256) {
            int n = i & 127, kk = i >> 7;
            float v = W2[(64 * c2 + kk) * H_ + n];
            uint32_t h, m;
            tsplit(v, h, m);
            wh[n * WPAD2 + kk] = h;
            wm[n * WPAD2 + kk] = m;
        }
        __syncthreads();

        #pragma unroll 4
        for (int ks = 0; ks < 8; ks++) {
            int kg = 64 * c2 + ks * 8;
            int kl = ks * 8;
            uint32_t ah[4], am[4];
            tsplit(uBuf[ur0 + kg + gc],     ah[0], am[0]);
            tsplit(uBuf[ur1 + kg + gc],     ah[1], am[1]);
            tsplit(uBuf[ur0 + kg + 4 + gc], ah[2], am[2]);
            tsplit(uBuf[ur1 + kg + 4 + gc], ah[3], am[3]);
            #pragma unroll
            for (int nf = 0; nf < 8; nf++) {
                int n = wx * 64 + nf * 8 + gr;
                uint32_t bh[2], bm[2];
                bh[0] = wh[n * WPAD2 + kl + gc];
                bm[0] = wm[n * WPAD2 + kl + gc];
                bh[1] = wh[n * WPAD2 + kl + 4 + gc];
                bm[1] = wm[n * WPAD2 + kl + 4 + gc];
                mma_tf32(acc2[nf], ah, bh);
                mma_tf32(acc2[nf], ah, bm);
                mma_tf32(acc2[nf], am, bh);
                mma_tf32(acc2[nf], am, bm);
            }
        }
    }

    __syncthreads();
    float* yBuf = (float*)wh;
    #pragma unroll
    for (int nf = 0; nf < 8; nf++)
        #pragma unroll
        for (int j = 0; j < 4; j++) {
            int row = wy * 16 + gr + ((j >> 1) ? 8 : 0);
            int col = wx * 64 + nf * 8 + gc * 2 + (j & 1);
            yBuf[row * EPAD + col] = acc2[nf][j] + __ldg(b2 + col) + eBuf[row * EPAD + col];
        }
    __syncthreads();

    #pragma unroll
    for (int rr = 0; rr < 8; rr++) {
        int row = w * 8 + rr;
        float v[4];
        #pragma unroll
        for (int q = 0; q < 4; q++) v[q] = yBuf[row * EPAD + lane + 32 * q];
        float s = v[0] + v[1] + v[2] + v[3];
        #pragma unroll
        for (int o = 16; o; o >>= 1) s += __shfl_xor_sync(0xffffffffu, s, o);
        float mu = s * (1.f / 128.f);
        float d[4], sq = 0.f;
        #pragma unroll
        for (int q = 0; q < 4; q++) { d[q] = v[q] - mu; sq = fmaf(d[q], d[q], sq); }
        #pragma unroll
        for (int o = 16; o; o >>= 1) sq += __shfl_xor_sync(0xffffffffu, sq, o);
        float inv = rsqrtf(sq * (1.f / 128.f) + 1e-5f);
        size_t base = (size_t)(tok0 + row) * H_;
        #pragma unroll
        for (int q = 0; q < 4; q++) {
            int col = lane + 32 * q;
            g_h[base + col] = d[q] * inv * __ldg(gamma + col) + __ldg(beta + col);
        }
    }
}

// =====================================================================
// Scan v3: 2 barriers/step, double-buffered k/red_k, 3-deep prefetch.
// Every FP value is computed by the SAME expression in the SAME order
// as the R1/R5 scan (bit-identical); only scheduling changed.
// =====================================================================
__global__ void __launch_bounds__(256, 2) scan_kernel()
{
    __shared__ float k_s[2][128];
    __shared__ float red_k[2][4];
    __shared__ float err_s[128];
    __shared__ float red_e[4];
    __shared__ float vp_part[128][17];

    const int bb   = blockIdx.x;
    const int tid  = threadIdx.x;
    const int ty   = tid >> 4, tx = tid & 15;
    const int lane = tid & 31;
    const float* __restrict__ hb = g_h + (size_t)bb * L_ * H_;

    float M[8][8];
    #pragma unroll
    for (int r = 0; r < 8; r++)
        #pragma unroll
        for (int c = 0; c < 8; c++) M[r][c] = 0.f;

    float kn0 = 0.f, kn1 = 0.f;
    if (tid < 128) {
        float kv = hb[tid];                       // h[0]
        k_s[0][tid] = kv;
        float p = kv * kv;
        #pragma unroll
        for (int o = 16; o; o >>= 1) p += __shfl_xor_sync(0xffffffffu, p, o);
        if (lane == 0) red_k[0][tid >> 5] = p;
        kn0 = hb[128 + tid];                      // h[1]
        kn1 = hb[256 + tid];                      // h[2]
    }
    __syncthreads();

    for (int t = 0; t < L_ - 1; t++) {
        const int buf = t & 1;

        // ---- phase 1: matvec partials + stage next k + next kk-reduce ----
        float kreg[8];
        #pragma unroll
        for (int c = 0; c < 8; c++) kreg[c] = k_s[buf][tx * 8 + c];
        #pragma unroll
        for (int r = 0; r < 8; r++) {
            float s = 0.f;
            #pragma unroll
            for (int c = 0; c < 8; c++) s = fmaf(M[r][c], kreg[c], s);
            vp_part[ty * 8 + r][tx] = s;
        }
        if (tid < 128) {
            k_s[buf ^ 1][tid] = kn0;              // h[t+1]
            float p = kn0 * kn0;                  // identical to R1's kv*kv at step t+1
            #pragma unroll
            for (int o = 16; o; o >>= 1) p += __shfl_xor_sync(0xffffffffu, p, o);
            if (lane == 0) red_k[buf ^ 1][tid >> 5] = p;
            kn0 = kn1;
            kn1 = (t + 3 < L_) ? hb[(size_t)(t + 3) * H_ + tid] : 0.f;
        }
        __syncthreads();                          // A: vp_part, k staging visible

        // kk readable by ALL threads here (red_k[buf] stable until phase1 of t+1)
        const float kk = red_k[buf][0] + red_k[buf][1] + red_k[buf][2] + red_k[buf][3];

        // ---- phase 2: row sums + err + e2-reduce (warps 0-3) ----
        if (tid < 128) {
            float vp = 0.f;
            #pragma unroll
            for (int x = 0; x < 16; x++) vp += vp_part[tid][x];
            float e = k_s[buf][tid] - vp / (kk + 1e-6f);
            err_s[tid] = e;
            float p = e * e;
            #pragma unroll
            for (int o = 16; o; o >>= 1) p += __shfl_xor_sync(0xffffffffu, p, o);
            if (lane == 0) red_e[tid >> 5] = p;
        }
        __syncthreads();                          // B: err_s, red_e visible

        // ---- gated rank-1 update (all threads) ----
        float e2 = red_e[0] + red_e[1] + red_e[2] + red_e[3];
        if (sqrtf(e2) > 0.4f * sqrtf(kk)) {
            float er[8];
            #pragma unroll
            for (int r = 0; r < 8; r++) er[r] = err_s[ty * 8 + r];
            #pragma unroll
            for (int r = 0; r < 8; r++)
                #pragma unroll
                for (int c = 0; c < 8; c++) M[r][c] = fmaf(er[r], kreg[c], M[r][c]);
        }
    }

    // ---- final: r = M @ h[L-1] ----
    {
        const int buf = (L_ - 1) & 1;
        float kreg[8];
        #pragma unroll
        for (int c = 0; c < 8; c++) kreg[c] = k_s[buf][tx * 8 + c];
        #pragma unroll
        for (int r = 0; r < 8; r++) {
            float s = 0.f;
            #pragma unroll
            for (int c = 0; c < 8; c++) s = fmaf(M[r][c], kreg[c], s);
            vp_part[ty * 8 + r][tx] = s;
        }
        __syncthreads();
        if (tid < 128) {
            float vp = 0.f;
            #pragma unroll
            for (int x = 0; x < 16; x++) vp += vp_part[tid][x];
            g_r[bb * H_ + tid] = vp;
        }
    }
}

// =====================================================================
// Kernel 3: r2 = r @ Wrp + brp
// =====================================================================
__global__ void __launch_bounds__(256, 1) rproj_kernel(
    const float* __restrict__ Wrp, const float* __restrict__ brp)
{
    extern __shared__ float smf[];
    float* Rs = smf;
    float* Ws = smf + 64 * 132;
    const int tid = threadIdx.x, ty = tid >> 4, tx = tid & 15;
    const int m0 = blockIdx.x * 64;

    for (int i = tid; i < 64 * 128; i += 256) {
        int r = i >> 7, c = i & 127;
        Rs[r * 132 + c] = g_r[(m0 + r) * H_ + c];
    }
    for (int i = tid; i < 128 * 128; i += 256) Ws[i] = Wrp[i];
    __syncthreads();

    float acc[4][8];
    #pragma unroll
    for (int r = 0; r < 4; r++)
        #pragma unroll
        for (int j = 0; j < 8; j++) acc[r][j] = 0.f;
    #pragma unroll 8
    for (int k = 0; k < 128; k++) {
        float a[4], bbv[8];
        #pragma unroll
        for (int r = 0; r < 4; r++) a[r] = Rs[(ty * 4 + r) * 132 + k];
        #pragma unroll
        for (int j = 0; j < 8; j++) bbv[j] = Ws[k * 128 + tx + 16 * j];
        #pragma unroll
        for (int r = 0; r < 4; r++)
            #pragma unroll
            for (int j = 0; j < 8; j++) acc[r][j] = fmaf(a[r], bbv[j], acc[r][j]);
    }
    #pragma unroll
    for (int r = 0; r < 4; r++)
        #pragma unroll
        for (int j = 0; j < 8; j++) {
            int rr = m0 + ty * 4 + r, cc = tx + 16 * j;
            g_r2[rr * H_ + cc] = acc[r][j] + brp[cc];
        }
}

// =====================================================================
// Kernel 4: out = r2 @ Wout + bout
// =====================================================================
__global__ void __launch_bounds__(256, 1) out_kernel(
    const float* __restrict__ Wout, const float* __restrict__ bout,
    float* __restrict__ out)
{
    extern __shared__ float smf[];
    float* Rs = smf;
    float* Ws = smf + 64 * 132;
    const int tid = threadIdx.x, ty = tid >> 4, tx = tid & 15;
    const int n0 = blockIdx.x * 128;
    const int m0 = blockIdx.y * 64;

    for (int i = tid; i < 64 * 128; i += 256) {
        int r = i >> 7, c = i & 127;
        Rs[r * 132 + c] = g_r2[(m0 + r) * H_ + c];
    }
    for (int i = tid; i < 128 * 128; i += 256) {
        int k = i >> 7, c = i & 127;
        Ws[i] = Wout[(size_t)k * V_ + n0 + c];
    }
    __syncthreads();

    float acc[4][8];
    #pragma unroll
    for (int r = 0; r < 4; r++)
        #pragma unroll
        for (int j = 0; j < 8; j++) acc[r][j] = 0.f;
    #pragma unroll 8
    for (int k = 0; k < 128; k++) {
        float a[4], bbv[8];
        #pragma unroll
        for (int r = 0; r < 4; r++) a[r] = Rs[(ty * 4 + r) * 132 + k];
        #pragma unroll
        for (int j = 0; j < 8; j++) bbv[j] = Ws[k * 128 + tx + 16 * j];
        #pragma unroll
        for (int r = 0; r < 4; r++)
            #pragma unroll
            for (int j = 0; j < 8; j++) acc[r][j] = fmaf(a[r], bbv[j], acc[r][j]);
    }
    #pragma unroll
    for (int r = 0; r < 4; r++)
        #pragma unroll
        for (int j = 0; j < 8; j++) {
            int rr = m0 + ty * 4 + r, cc = n0 + tx + 16 * j;
            out[(size_t)rr * V_ + cc] = acc[r][j] + bout[cc];
        }
}

// =====================================================================
// launcher
// =====================================================================
extern "C" void kernel_launch(void* const* d_in, const int* in_sizes, int n_in,
                              void* d_out, int out_size)
{
    const int*   seq   = (const int*)  d_in[0];
    const float* embed = (const float*)d_in[1];
    const float* W1    = (const float*)d_in[2];
    const float* b1    = (const float*)d_in[3];
    const float* W2    = (const float*)d_in[4];
    const float* b2    = (const float*)d_in[5];
    const float* gamma = (const float*)d_in[6];
    const float* beta  = (const float*)d_in[7];
    const float* Wrp   = (const float*)d_in[8];
    const float* brp   = (const float*)d_in[9];
    const float* Wout  = (const float*)d_in[10];
    const float* bout  = (const float*)d_in[11];
    float* out = (float*)d_out;

    const int PROJ_SMEM = (64 * 132 + 128 * 128) * 4;

    cudaFuncSetAttribute(encode_mma,   cudaFuncAttributeMaxDynamicSharedMemorySize, ENC_SMEM);
    cudaFuncSetAttribute(rproj_kernel, cudaFuncAttributeMaxDynamicSharedMemorySize, PROJ_SMEM);
    cudaFuncSetAttribute(out_kernel,   cudaFuncAttributeMaxDynamicSharedMemorySize, PROJ_SMEM);

    encode_mma<<<(B_ * L_) / 64, 256, ENC_SMEM>>>(seq, embed, W1, b1, W2, b2, gamma, beta);
    scan_kernel<<<B_, 256>>>();
    rproj_kernel<<<B_ / 64, 256, PROJ_SMEM>>>(Wrp, brp);
    out_kernel<<<dim3(V_ / 128, B_ / 64), 256, PROJ_SMEM>>>(Wout, bout, out);
}